// round 13
// baseline (speedup 1.0000x reference)
#include <cuda_runtime.h>
#include <cuda_bf16.h>
#include <cstdint>

#define NN 50000
#define NE 800000
#define CAP 64
#define HALF1 25088            // first-half node/row count (multiple of 128 and 8)

// ---------------- scratch (device globals: no allocation) ----------------
__device__ __align__(16) float          g_tmpA[NN * 512];  // GEMM out, layers 1 & 3
__device__ __align__(16) float          g_tmpB[NN * 256];  // GEMM out, layers 2 & 4 (<=256 cols)
__device__ __align__(16) __nv_bfloat16  g_ahi[NN * 512];   // activation hi split
__device__ __align__(16) __nv_bfloat16  g_alo[NN * 512];   // activation lo split
__device__ int            g_cnt[NN];
__device__ int            g_bsrc[NN * CAP];
__device__ float          g_bw[NN * CAP];
__device__ int            g_beid[NN * CAP];                // edge id per slot (canonical order)
// transposed weights (bf16 hi/lo), [N,K] layout, packed:
// L1 off 0 (512*512), L2 off 262144 (256*512), L3 off 393216 (128*256), L4 off 425984 (64*128)
__device__ __align__(16) __nv_bfloat16  g_bthi[434176];
__device__ __align__(16) __nv_bfloat16  g_btlo[434176];

// ---------------- side stream + events (created pre-main) ----------------
struct SideRes {
    cudaStream_t s;
    cudaEvent_t fork, bk, s1a, s1b, s2a, s2b, s3a, s3b, end;
    SideRes() {
        cudaStreamCreate(&s);
        cudaEvent_t* evs[9] = {&fork, &bk, &s1a, &s1b, &s2a, &s2b, &s3a, &s3b, &end};
        for (int i = 0; i < 9; i++) cudaEventCreateWithFlags(evs[i], cudaEventDisableTiming);
    }
};
static SideRes g_side;

// ---------------- PTX helpers (baseline sm_80+ PTX only) ----------------
__device__ __forceinline__ uint32_t smem_to_u32(const void* p) {
    uint32_t a;
    asm("{ .reg .u64 t; cvta.to.shared.u64 t, %1; cvt.u32.u64 %0, t; }" : "=r"(a) : "l"(p));
    return a;
}

#define CP_ASYNC16(dst, src) \
    asm volatile("cp.async.cg.shared.global [%0], [%1], 16;" :: "r"(dst), "l"(src) : "memory")
#define CP_COMMIT() asm volatile("cp.async.commit_group;" ::: "memory")
#define CP_WAIT1()  asm volatile("cp.async.wait_group 1;" ::: "memory")

#define LDSM_X4(r0, r1, r2, r3, addr) \
    asm volatile("ldmatrix.sync.aligned.m8n8.x4.shared.b16 {%0,%1,%2,%3}, [%4];" \
                 : "=r"(r0), "=r"(r1), "=r"(r2), "=r"(r3) : "r"(addr))

#define MMA_BF16(d, a, b) \
    asm volatile("mma.sync.aligned.m16n8k16.row.col.f32.bf16.bf16.f32 " \
                 "{%0,%1,%2,%3}, {%4,%5,%6,%7}, {%8,%9}, {%0,%1,%2,%3};" \
                 : "+f"((d)[0]), "+f"((d)[1]), "+f"((d)[2]), "+f"((d)[3]) \
                 : "r"((a)[0]), "r"((a)[1]), "r"((a)[2]), "r"((a)[3]), \
                   "r"((b)[0]), "r"((b)[1]))

// ---------------- prep kernels ----------------
__global__ void zero_cnt_kernel(int* cnt, int n) {
    int i = blockIdx.x * blockDim.x + threadIdx.x;
    if (i < n) cnt[i] = 0;
}

__global__ void scatter_edges_kernel(const int* __restrict__ esrc, const int* __restrict__ edst,
                                     const float* __restrict__ ew, int* __restrict__ cnt,
                                     int* __restrict__ bsrc, float* __restrict__ bw,
                                     int* __restrict__ beid) {
    int e = blockIdx.x * blockDim.x + threadIdx.x;
    if (e >= NE) return;
    int d = edst[e];
    int p = atomicAdd(&cnt[d], 1);
    if (p < CAP) {
        bsrc[d * CAP + p] = esrc[e];
        bw[d * CAP + p]   = ew[e];
        beid[d * CAP + p] = e;
    }
}

// Canonicalize bucket order: rank-sort each node's bucket by edge id.
__global__ void sort_buckets_kernel(const int* __restrict__ cnt, int* __restrict__ bsrc,
                                    float* __restrict__ bw, const int* __restrict__ beid) {
    __shared__ int   se[CAP];
    __shared__ int   ss[CAP];
    __shared__ float sw[CAP];
    int node = blockIdx.x;
    int deg = cnt[node];
    if (deg > CAP) deg = CAP;
    int t = threadIdx.x;
    if (t < deg) {
        se[t] = beid[node * CAP + t];
        ss[t] = bsrc[node * CAP + t];
        sw[t] = bw[node * CAP + t];
    }
    __syncthreads();
    if (t < deg) {
        int my = se[t];
        int r = 0;
        for (int j = 0; j < deg; j++) r += (se[j] < my);
        bsrc[node * CAP + r] = ss[t];
        bw[node * CAP + r]   = sw[t];
    }
}

// fp32 -> bf16 hi/lo split (vectorized by 4)
__global__ void conv_hilo_kernel(const float4* __restrict__ in, uint2* __restrict__ oh,
                                 uint2* __restrict__ ol, int n4) {
    int i = blockIdx.x * blockDim.x + threadIdx.x;
    if (i >= n4) return;
    float4 v = in[i];
    __nv_bfloat16 hx = __float2bfloat16(v.x), hy = __float2bfloat16(v.y);
    __nv_bfloat16 hz = __float2bfloat16(v.z), hw = __float2bfloat16(v.w);
    float lx = v.x - __bfloat162float(hx), ly = v.y - __bfloat162float(hy);
    float lz = v.z - __bfloat162float(hz), lw = v.w - __bfloat162float(hw);
    __nv_bfloat162 h0 = __nv_bfloat162(hx, hy), h1 = __nv_bfloat162(hz, hw);
    __nv_bfloat162 l0 = __nv_bfloat162(__float2bfloat16(lx), __float2bfloat16(ly));
    __nv_bfloat162 l1 = __nv_bfloat162(__float2bfloat16(lz), __float2bfloat16(lw));
    uint2 ph, pl;
    ph.x = *reinterpret_cast<uint32_t*>(&h0); ph.y = *reinterpret_cast<uint32_t*>(&h1);
    pl.x = *reinterpret_cast<uint32_t*>(&l0); pl.y = *reinterpret_cast<uint32_t*>(&l1);
    oh[i] = ph; ol[i] = pl;
}

// All four W [K,N] fp32 -> Bt_hi/Bt_lo [N,K] bf16, one launch.
__global__ void convW_all_kernel(const float* __restrict__ W1, const float* __restrict__ W2,
                                 const float* __restrict__ W3, const float* __restrict__ W4,
                                 __nv_bfloat16* __restrict__ oh, __nv_bfloat16* __restrict__ ol) {
    __shared__ float t[32][33];
    int layer = blockIdx.z;
    const float* W; int K, N, off;
    if (layer == 0)      { W = W1; K = 512; N = 512; off = 0; }
    else if (layer == 1) { W = W2; K = 512; N = 256; off = 262144; }
    else if (layer == 2) { W = W3; K = 256; N = 128; off = 393216; }
    else                 { W = W4; K = 128; N = 64;  off = 425984; }
    int nbx = N >> 5;
    if ((int)blockIdx.x >= nbx * (K >> 5)) return;
    int n0 = (blockIdx.x % nbx) * 32;
    int k0 = (blockIdx.x / nbx) * 32;
    int tx = threadIdx.x, ty = threadIdx.y;   // block (32,8)
#pragma unroll
    for (int i = 0; i < 4; i++)
        t[ty + i * 8][tx] = W[(long long)(k0 + ty + i * 8) * N + n0 + tx];
    __syncthreads();
#pragma unroll
    for (int i = 0; i < 4; i++) {
        float v = t[tx][ty + i * 8];
        __nv_bfloat16 h = __float2bfloat16(v);
        float l = v - __bfloat162float(h);
        long long o = off + (long long)(n0 + ty + i * 8) * K + k0 + tx;
        oh[o] = h;
        ol[o] = __float2bfloat16(l);
    }
}

// ---------------- mma.sync split-bf16 GEMM (R4-proven shape): C[M,N] = A @ Bt^T ----------------
// CTA: 128(M) x 64(N), 256 threads; K chunks of 64, cp.async double-buffered.
#define STAGE_BYTES 49152

__device__ __forceinline__ void issue_stage(
    const __nv_bfloat16* Ahi, const __nv_bfloat16* Alo,
    const __nv_bfloat16* Bhi, const __nv_bfloat16* Blo,
    uint32_t sbase, int stage, int kc, int row0, int col0, int M, int K, int tid) {
    int k0 = kc << 6;
    uint32_t sA = sbase + stage * STAGE_BYTES;
    uint32_t sB = sA + 32768;
#pragma unroll
    for (int i = 0; i < 8; i++) {               // A: 2048 x 16B
        int f = tid + i * 256;
        int split = f >> 10, r = (f >> 3) & 127, c = f & 7;
        int gr = row0 + r; if (gr >= M) gr = M - 1;
        const __nv_bfloat16* src = (split ? Alo : Ahi) + (size_t)gr * K + k0 + c * 8;
        uint32_t dst = sA + split * 16384 + r * 128 + (((c ^ (r & 7)) << 4));
        CP_ASYNC16(dst, src);
    }
#pragma unroll
    for (int i = 0; i < 4; i++) {               // B: 1024 x 16B
        int f = tid + i * 256;
        int split = f >> 9, r = (f >> 3) & 63, c = f & 7;
        int gn = col0 + r;
        const __nv_bfloat16* src = (split ? Blo : Bhi) + (size_t)gn * K + k0 + c * 8;
        uint32_t dst = sB + split * 8192 + r * 128 + (((c ^ (r & 7)) << 4));
        CP_ASYNC16(dst, src);
    }
    CP_COMMIT();
}

__global__ __launch_bounds__(256, 2)
void gemm_mma_kernel(const __nv_bfloat16* __restrict__ Ahi, const __nv_bfloat16* __restrict__ Alo,
                     const __nv_bfloat16* __restrict__ Bhi, const __nv_bfloat16* __restrict__ Blo,
                     float* __restrict__ C, int M, int K, int N, int row_base) {
    extern __shared__ __align__(1024) char smem[];
    uint32_t sbase = smem_to_u32(smem);
    int tid = threadIdx.x, wid = tid >> 5, lid = tid & 31;
    int mwarp = wid & 3, nwarp = wid >> 2;
    int row0 = row_base + blockIdx.y * 128;
    int col0 = blockIdx.x * 64;

    float acc[2][4][4];
#pragma unroll
    for (int mt = 0; mt < 2; mt++)
#pragma unroll
        for (int nt = 0; nt < 4; nt++)
#pragma unroll
            for (int q = 0; q < 4; q++) acc[mt][nt][q] = 0.0f;

    const int nchunks = K >> 6;

    issue_stage(Ahi, Alo, Bhi, Blo, sbase, 0, 0, row0, col0, M, K, tid);
    issue_stage(Ahi, Alo, Bhi, Blo, sbase, 1, 1, row0, col0, M, K, tid);

    int raA = mwarp * 32 + (lid & 15);
    int caA = lid >> 4;
    int rbB = nwarp * 32 + ((lid >> 4) << 3) + (lid & 7);
    int cbB = (lid >> 3) & 1;

    for (int kc = 0; kc < nchunks; kc++) {
        CP_WAIT1();
        __syncthreads();
        int stage = kc & 1;
        uint32_t aB = sbase + stage * STAGE_BYTES;
        uint32_t bB = aB + 32768;

#pragma unroll
        for (int k16 = 0; k16 < 4; k16++) {
            uint32_t ah[2][4], al[2][4];
#pragma unroll
            for (int mt = 0; mt < 2; mt++) {
                int r = raA + mt * 16;
                int c = caA + k16 * 2;
                uint32_t off = r * 128 + (((c ^ (r & 7)) << 4));
                LDSM_X4(ah[mt][0], ah[mt][1], ah[mt][2], ah[mt][3], aB + off);
                LDSM_X4(al[mt][0], al[mt][1], al[mt][2], al[mt][3], aB + 16384 + off);
            }
            uint32_t bh[4][2], bl[4][2];
#pragma unroll
            for (int ntp = 0; ntp < 2; ntp++) {
                int r = rbB + ntp * 16;
                int c = cbB + k16 * 2;
                uint32_t off = r * 128 + (((c ^ (r & 7)) << 4));
                LDSM_X4(bh[2 * ntp][0], bh[2 * ntp][1], bh[2 * ntp + 1][0], bh[2 * ntp + 1][1], bB + off);
                LDSM_X4(bl[2 * ntp][0], bl[2 * ntp][1], bl[2 * ntp + 1][0], bl[2 * ntp + 1][1], bB + 8192 + off);
            }
#pragma unroll
            for (int mt = 0; mt < 2; mt++)
#pragma unroll
                for (int nt = 0; nt < 4; nt++) {
                    MMA_BF16(acc[mt][nt], ah[mt], bh[nt]);
                    MMA_BF16(acc[mt][nt], ah[mt], bl[nt]);
                    MMA_BF16(acc[mt][nt], al[mt], bh[nt]);
                }
        }
        __syncthreads();
        if (kc + 2 < nchunks)
            issue_stage(Ahi, Alo, Bhi, Blo, sbase, stage, kc + 2, row0, col0, M, K, tid);
    }

    int g = lid >> 2, t2 = (lid & 3) * 2;
#pragma unroll
    for (int mt = 0; mt < 2; mt++) {
        int r0g = row0 + mwarp * 32 + mt * 16 + g;
#pragma unroll
        for (int nt = 0; nt < 4; nt++) {
            int cn = col0 + nwarp * 32 + nt * 8 + t2;
            if (r0g < M)
                *reinterpret_cast<float2*>(&C[(size_t)r0g * N + cn]) =
                    make_float2(acc[mt][nt][0], acc[mt][nt][1]);
            if (r0g + 8 < M)
                *reinterpret_cast<float2*>(&C[(size_t)(r0g + 8) * N + cn]) =
                    make_float2(acc[mt][nt][2], acc[mt][nt][3]);
        }
    }
}

// ---------------- SPMM + bias (+ReLU); NVEC = D/4; 128/NVEC nodes per 128-thread block ----------------
template <int NVEC>
__global__ void spmm_kernel(const float* __restrict__ tmp, const int* __restrict__ cnt,
                            const int* __restrict__ bsrc, const float* __restrict__ bw,
                            const float* __restrict__ bias,
                            float* __restrict__ outf,
                            __nv_bfloat16* __restrict__ oh, __nv_bfloat16* __restrict__ ol,
                            int do_relu, int split, int node_base) {
    constexpr int NPB = 128 / NVEC;
    int sub = threadIdx.x / NVEC;
    int c = threadIdx.x % NVEC;
    int node = node_base + blockIdx.x * NPB + sub;
    if (node >= NN) return;
    int deg = cnt[node];
    if (deg > CAP) deg = CAP;
    const float4* t4 = reinterpret_cast<const float4*>(tmp);
    const float4* b4 = reinterpret_cast<const float4*>(bias);
    const int* __restrict__ bs = &bsrc[node * CAP];
    const float* __restrict__ bwp = &bw[node * CAP];

    float4 acc = make_float4(0.f, 0.f, 0.f, 0.f);
#pragma unroll 4
    for (int e = 0; e < deg; e++) {
        int s = bs[e];
        float w = bwp[e];
        float4 v = t4[(size_t)s * NVEC + c];
        acc.x = fmaf(w, v.x, acc.x);
        acc.y = fmaf(w, v.y, acc.y);
        acc.z = fmaf(w, v.z, acc.z);
        acc.w = fmaf(w, v.w, acc.w);
    }
    float4 bb = b4[c];
    acc.x += bb.x; acc.y += bb.y; acc.z += bb.z; acc.w += bb.w;
    if (do_relu) {
        acc.x = fmaxf(acc.x, 0.f); acc.y = fmaxf(acc.y, 0.f);
        acc.z = fmaxf(acc.z, 0.f); acc.w = fmaxf(acc.w, 0.f);
    }
    size_t o4 = (size_t)node * NVEC + c;
    if (split) {
        __nv_bfloat16 hx = __float2bfloat16(acc.x), hy = __float2bfloat16(acc.y);
        __nv_bfloat16 hz = __float2bfloat16(acc.z), hw = __float2bfloat16(acc.w);
        float lx = acc.x - __bfloat162float(hx), ly = acc.y - __bfloat162float(hy);
        float lz = acc.z - __bfloat162float(hz), lw = acc.w - __bfloat162float(hw);
        __nv_bfloat162 h0 = __nv_bfloat162(hx, hy), h1 = __nv_bfloat162(hz, hw);
        __nv_bfloat162 l0 = __nv_bfloat162(__float2bfloat16(lx), __float2bfloat16(ly));
        __nv_bfloat162 l1 = __nv_bfloat162(__float2bfloat16(lz), __float2bfloat16(lw));
        uint2 ph, pl;
        ph.x = *reinterpret_cast<uint32_t*>(&h0); ph.y = *reinterpret_cast<uint32_t*>(&h1);
        pl.x = *reinterpret_cast<uint32_t*>(&l0); pl.y = *reinterpret_cast<uint32_t*>(&l1);
        reinterpret_cast<uint2*>(oh)[o4] = ph;
        reinterpret_cast<uint2*>(ol)[o4] = pl;
    } else {
        reinterpret_cast<float4*>(outf)[o4] = acc;
    }
}

// ---------------- launch ----------------
extern "C" void kernel_launch(void* const* d_in, const int* in_sizes, int n_in,
                              void* d_out, int out_size) {
    const float* x    = (const float*)d_in[0];
    const int*   esrc = (const int*)d_in[1];
    const int*   edst = (const int*)d_in[2];
    const float* ew   = (const float*)d_in[3];
    const float* W1 = (const float*)d_in[4];  const float* b1 = (const float*)d_in[5];
    const float* W2 = (const float*)d_in[6];  const float* b2 = (const float*)d_in[7];
    const float* W3 = (const float*)d_in[8];  const float* b3 = (const float*)d_in[9];
    const float* W4 = (const float*)d_in[10]; const float* b4 = (const float*)d_in[11];
    float* out = (float*)d_out;

    float *tmpA, *tmpB, *bw;
    __nv_bfloat16 *ahi, *alo, *bthi, *btlo;
    int *cnt, *bsrc, *beid;
    cudaGetSymbolAddress((void**)&tmpA, g_tmpA);
    cudaGetSymbolAddress((void**)&tmpB, g_tmpB);
    cudaGetSymbolAddress((void**)&ahi,  g_ahi);
    cudaGetSymbolAddress((void**)&alo,  g_alo);
    cudaGetSymbolAddress((void**)&cnt,  g_cnt);
    cudaGetSymbolAddress((void**)&bsrc, g_bsrc);
    cudaGetSymbolAddress((void**)&bw,   g_bw);
    cudaGetSymbolAddress((void**)&beid, g_beid);
    cudaGetSymbolAddress((void**)&bthi, g_bthi);
    cudaGetSymbolAddress((void**)&btlo, g_btlo);

    const int SMEM = 2 * STAGE_BYTES;   // 98304
    cudaFuncSetAttribute(gemm_mma_kernel, cudaFuncAttributeMaxDynamicSharedMemorySize, SMEM);

    cudaStream_t B = g_side.s;
    const int MB1 = HALF1 / 128;                 // 196 row tiles, rows [0, 25088)
    const int MB2 = (NN - HALF1 + 127) / 128;    // 195 row tiles, rows [25088, 50000)

    // ---- fork: edge bucketing + canonical ordering on side stream B ----
    cudaEventRecord(g_side.fork, 0);
    cudaStreamWaitEvent(B, g_side.fork, 0);
    zero_cnt_kernel<<<(NN + 255) / 256, 256, 0, B>>>(cnt, NN);
    scatter_edges_kernel<<<(NE + 255) / 256, 256, 0, B>>>(esrc, edst, ew, cnt, bsrc, bw, beid);
    sort_buckets_kernel<<<NN, CAP, 0, B>>>(cnt, bsrc, bw, beid);
    cudaEventRecord(g_side.bk, B);

    // ---- main stream M: conversions + GEMM-1 -> tmpA (overlaps bucketing) ----
    convW_all_kernel<<<dim3(16 * 16, 1, 4), dim3(32, 8)>>>(W1, W2, W3, W4, bthi, btlo);
    conv_hilo_kernel<<<(NN * 128 + 255) / 256, 256>>>((const float4*)x, (uint2*)ahi, (uint2*)alo, NN * 128);
    gemm_mma_kernel<<<dim3(8, 391), 256, SMEM>>>(ahi, alo, bthi, btlo, tmpA, NN, 512, 512, 0);

    // ---- M: SPMM-1 halves (read tmpA) ----
    cudaStreamWaitEvent(0, g_side.bk, 0);
    spmm_kernel<128><<<HALF1, 128>>>(tmpA, cnt, bsrc, bw, b1, nullptr, ahi, alo, 1, 1, 0);
    cudaEventRecord(g_side.s1a, 0);
    spmm_kernel<128><<<NN - HALF1, 128>>>(tmpA, cnt, bsrc, bw, b1, nullptr, ahi, alo, 1, 1, HALF1);
    cudaEventRecord(g_side.s1b, 0);

    // ---- B: GEMM-2 halves -> tmpB (h1 overlaps S1h2; tmpB disjoint from tmpA) + SPMM-2 (read tmpB) ----
    cudaStreamWaitEvent(B, g_side.s1a, 0);
    gemm_mma_kernel<<<dim3(4, MB1), 256, SMEM, B>>>(ahi, alo, bthi + 262144, btlo + 262144, tmpB, NN, 512, 256, 0);
    cudaStreamWaitEvent(B, g_side.s1b, 0);
    gemm_mma_kernel<<<dim3(4, MB2), 256, SMEM, B>>>(ahi, alo, bthi + 262144, btlo + 262144, tmpB, NN, 512, 256, HALF1);
    spmm_kernel<64><<<HALF1 / 2, 128, 0, B>>>(tmpB, cnt, bsrc, bw, b2, nullptr, ahi, alo, 1, 1, 0);
    cudaEventRecord(g_side.s2a, B);
    spmm_kernel<64><<<(NN - HALF1 + 1) / 2, 128, 0, B>>>(tmpB, cnt, bsrc, bw, b2, nullptr, ahi, alo, 1, 1, HALF1);
    cudaEventRecord(g_side.s2b, B);

    // ---- M: GEMM-3 halves -> tmpA (h1 overlaps S2h2; tmpA disjoint from tmpB) + SPMM-3 (read tmpA) ----
    cudaStreamWaitEvent(0, g_side.s2a, 0);
    gemm_mma_kernel<<<dim3(2, MB1), 256, SMEM>>>(ahi, alo, bthi + 393216, btlo + 393216, tmpA, NN, 256, 128, 0);
    cudaStreamWaitEvent(0, g_side.s2b, 0);
    gemm_mma_kernel<<<dim3(2, MB2), 256, SMEM>>>(ahi, alo, bthi + 393216, btlo + 393216, tmpA, NN, 256, 128, HALF1);
    spmm_kernel<32><<<HALF1 / 4, 128>>>(tmpA, cnt, bsrc, bw, b3, nullptr, ahi, alo, 1, 1, 0);
    cudaEventRecord(g_side.s3a, 0);
    spmm_kernel<32><<<(NN - HALF1 + 3) / 4, 128>>>(tmpA, cnt, bsrc, bw, b3, nullptr, ahi, alo, 1, 1, HALF1);
    cudaEventRecord(g_side.s3b, 0);

    // ---- B: GEMM-4 halves -> tmpB (h1 overlaps S3h2) + SPMM-4 (read tmpB, write d_out) ----
    cudaStreamWaitEvent(B, g_side.s3a, 0);
    gemm_mma_kernel<<<dim3(1, MB1), 256, SMEM, B>>>(ahi, alo, bthi + 425984, btlo + 425984, tmpB, NN, 128, 64, 0);
    cudaStreamWaitEvent(B, g_side.s3b, 0);
    gemm_mma_kernel<<<dim3(1, MB2), 256, SMEM, B>>>(ahi, alo, bthi + 425984, btlo + 425984, tmpB, NN, 128, 64, HALF1);
    spmm_kernel<16><<<HALF1 / 8, 128, 0, B>>>(tmpB, cnt, bsrc, bw, b4, out, nullptr, nullptr, 0, 0, 0);
    spmm_kernel<16><<<(NN - HALF1 + 7) / 8, 128, 0, B>>>(tmpB, cnt, bsrc, bw, b4, out, nullptr, nullptr, 0, 0, HALF1);
    cudaEventRecord(g_side.end, B);

    // ---- join back to capture stream ----
    cudaStreamWaitEvent(0, g_side.end, 0);

    (void)in_sizes; (void)n_in; (void)out_size;
}

// round 14
// speedup vs baseline: 1.0079x; 1.0079x over previous
#include <cuda_runtime.h>
#include <cuda_bf16.h>
#include <cstdint>

#define NN 50000
#define NE 800000
#define CAP 64

// ---------------- scratch (device globals: no allocation) ----------------
__device__ __align__(16) float          g_tmp[NN * 512];   // GEMM output (pre-agg), fp32
__device__ __align__(16) __nv_bfloat16  g_ahi[NN * 512];   // activation hi split
__device__ __align__(16) __nv_bfloat16  g_alo[NN * 512];   // activation lo split
__device__ int            g_cnt[NN];
__device__ __align__(16) int2 g_bpack[NN * CAP];           // packed (src, weight-bits) per slot
__device__ int            g_beid[NN * CAP];                // edge id per slot (canonical order)
// transposed weights (bf16 hi/lo), [N,K] layout, packed:
// L1 off 0 (512*512), L2 off 262144 (256*512), L3 off 393216 (128*256), L4 off 425984 (64*128)
__device__ __align__(16) __nv_bfloat16  g_bthi[434176];
__device__ __align__(16) __nv_bfloat16  g_btlo[434176];

// ---------------- side stream + events (created pre-main) ----------------
struct SideRes {
    cudaStream_t s;
    cudaEvent_t fork, evW, bk;
    SideRes() {
        cudaStreamCreate(&s);
        cudaEventCreateWithFlags(&fork, cudaEventDisableTiming);
        cudaEventCreateWithFlags(&evW,  cudaEventDisableTiming);
        cudaEventCreateWithFlags(&bk,   cudaEventDisableTiming);
    }
};
static SideRes g_side;

// ---------------- PTX helpers (baseline sm_80+ PTX only) ----------------
__device__ __forceinline__ uint32_t smem_to_u32(const void* p) {
    uint32_t a;
    asm("{ .reg .u64 t; cvta.to.shared.u64 t, %1; cvt.u32.u64 %0, t; }" : "=r"(a) : "l"(p));
    return a;
}

#define CP_ASYNC16(dst, src) \
    asm volatile("cp.async.cg.shared.global [%0], [%1], 16;" :: "r"(dst), "l"(src) : "memory")
#define CP_COMMIT() asm volatile("cp.async.commit_group;" ::: "memory")
#define CP_WAIT1()  asm volatile("cp.async.wait_group 1;" ::: "memory")

#define LDSM_X4(r0, r1, r2, r3, addr) \
    asm volatile("ldmatrix.sync.aligned.m8n8.x4.shared.b16 {%0,%1,%2,%3}, [%4];" \
                 : "=r"(r0), "=r"(r1), "=r"(r2), "=r"(r3) : "r"(addr))

#define MMA_BF16(d, a, b) \
    asm volatile("mma.sync.aligned.m16n8k16.row.col.f32.bf16.bf16.f32 " \
                 "{%0,%1,%2,%3}, {%4,%5,%6,%7}, {%8,%9}, {%0,%1,%2,%3};" \
                 : "+f"((d)[0]), "+f"((d)[1]), "+f"((d)[2]), "+f"((d)[3]) \
                 : "r"((a)[0]), "r"((a)[1]), "r"((a)[2]), "r"((a)[3]), \
                   "r"((b)[0]), "r"((b)[1]))

// ---------------- prep kernels ----------------
__global__ void zero_cnt_kernel(int* cnt, int n) {
    int i = blockIdx.x * blockDim.x + threadIdx.x;
    if (i < n) cnt[i] = 0;
}

__global__ void scatter_edges_kernel(const int* __restrict__ esrc, const int* __restrict__ edst,
                                     const float* __restrict__ ew, int* __restrict__ cnt,
                                     int2* __restrict__ bpack, int* __restrict__ beid) {
    int e = blockIdx.x * blockDim.x + threadIdx.x;
    if (e >= NE) return;
    int d = edst[e];
    int p = atomicAdd(&cnt[d], 1);
    if (p < CAP) {
        float w = ew[e];
        bpack[d * CAP + p] = make_int2(esrc[e], __float_as_int(w));
        beid[d * CAP + p]  = e;
    }
}

// Canonicalize bucket order: rank-sort each node's bucket by edge id.
__global__ void sort_buckets_kernel(const int* __restrict__ cnt, int2* __restrict__ bpack,
                                    const int* __restrict__ beid) {
    __shared__ int  se[CAP];
    __shared__ int2 sp[CAP];
    int node = blockIdx.x;
    int deg = cnt[node];
    if (deg > CAP) deg = CAP;
    int t = threadIdx.x;
    if (t < deg) {
        se[t] = beid[node * CAP + t];
        sp[t] = bpack[node * CAP + t];
    }
    __syncthreads();
    if (t < deg) {
        int my = se[t];
        int r = 0;
        for (int j = 0; j < deg; j++) r += (se[j] < my);
        bpack[node * CAP + r] = sp[t];
    }
}

// fp32 -> bf16 hi/lo split (vectorized by 4)
__global__ void conv_hilo_kernel(const float4* __restrict__ in, uint2* __restrict__ oh,
                                 uint2* __restrict__ ol, int n4) {
    int i = blockIdx.x * blockDim.x + threadIdx.x;
    if (i >= n4) return;
    float4 v = in[i];
    __nv_bfloat16 hx = __float2bfloat16(v.x), hy = __float2bfloat16(v.y);
    __nv_bfloat16 hz = __float2bfloat16(v.z), hw = __float2bfloat16(v.w);
    float lx = v.x - __bfloat162float(hx), ly = v.y - __bfloat162float(hy);
    float lz = v.z - __bfloat162float(hz), lw = v.w - __bfloat162float(hw);
    __nv_bfloat162 h0 = __nv_bfloat162(hx, hy), h1 = __nv_bfloat162(hz, hw);
    __nv_bfloat162 l0 = __nv_bfloat162(__float2bfloat16(lx), __float2bfloat16(ly));
    __nv_bfloat162 l1 = __nv_bfloat162(__float2bfloat16(lz), __float2bfloat16(lw));
    uint2 ph, pl;
    ph.x = *reinterpret_cast<uint32_t*>(&h0); ph.y = *reinterpret_cast<uint32_t*>(&h1);
    pl.x = *reinterpret_cast<uint32_t*>(&l0); pl.y = *reinterpret_cast<uint32_t*>(&l1);
    oh[i] = ph; ol[i] = pl;
}

// All four W [K,N] fp32 -> Bt_hi/Bt_lo [N,K] bf16, one launch.
__global__ void convW_all_kernel(const float* __restrict__ W1, const float* __restrict__ W2,
                                 const float* __restrict__ W3, const float* __restrict__ W4,
                                 __nv_bfloat16* __restrict__ oh, __nv_bfloat16* __restrict__ ol) {
    __shared__ float t[32][33];
    int layer = blockIdx.z;
    const float* W; int K, N, off;
    if (layer == 0)      { W = W1; K = 512; N = 512; off = 0; }
    else if (layer == 1) { W = W2; K = 512; N = 256; off = 262144; }
    else if (layer == 2) { W = W3; K = 256; N = 128; off = 393216; }
    else                 { W = W4; K = 128; N = 64;  off = 425984; }
    int nbx = N >> 5;
    if ((int)blockIdx.x >= nbx * (K >> 5)) return;
    int n0 = (blockIdx.x % nbx) * 32;
    int k0 = (blockIdx.x / nbx) * 32;
    int tx = threadIdx.x, ty = threadIdx.y;   // block (32,8)
#pragma unroll
    for (int i = 0; i < 4; i++)
        t[ty + i * 8][tx] = W[(long long)(k0 + ty + i * 8) * N + n0 + tx];
    __syncthreads();
#pragma unroll
    for (int i = 0; i < 4; i++) {
        float v = t[tx][ty + i * 8];
        __nv_bfloat16 h = __float2bfloat16(v);
        float l = v - __bfloat162float(h);
        long long o = off + (long long)(n0 + ty + i * 8) * K + k0 + tx;
        oh[o] = h;
        ol[o] = __float2bfloat16(l);
    }
}

// ---------------- mma.sync split-bf16 GEMM (R4-proven shape): C[M,N] = A @ Bt^T ----------------
// CTA: 128(M) x 64(N), 256 threads; K chunks of 64, cp.async double-buffered.
#define STAGE_BYTES 49152

__device__ __forceinline__ void issue_stage(
    const __nv_bfloat16* Ahi, const __nv_bfloat16* Alo,
    const __nv_bfloat16* Bhi, const __nv_bfloat16* Blo,
    uint32_t sbase, int stage, int kc, int row0, int col0, int M, int K, int tid) {
    int k0 = kc << 6;
    uint32_t sA = sbase + stage * STAGE_BYTES;
    uint32_t sB = sA + 32768;
#pragma unroll
    for (int i = 0; i < 8; i++) {               // A: 2048 x 16B
        int f = tid + i * 256;
        int split = f >> 10, r = (f >> 3) & 127, c = f & 7;
        int gr = row0 + r; if (gr >= M) gr = M - 1;
        const __nv_bfloat16* src = (split ? Alo : Ahi) + (size_t)gr * K + k0 + c * 8;
        uint32_t dst = sA + split * 16384 + r * 128 + (((c ^ (r & 7)) << 4));
        CP_ASYNC16(dst, src);
    }
#pragma unroll
    for (int i = 0; i < 4; i++) {               // B: 1024 x 16B
        int f = tid + i * 256;
        int split = f >> 9, r = (f >> 3) & 63, c = f & 7;
        int gn = col0 + r;
        const __nv_bfloat16* src = (split ? Blo : Bhi) + (size_t)gn * K + k0 + c * 8;
        uint32_t dst = sB + split * 8192 + r * 128 + (((c ^ (r & 7)) << 4));
        CP_ASYNC16(dst, src);
    }
    CP_COMMIT();
}

__global__ __launch_bounds__(256, 2)
void gemm_mma_kernel(const __nv_bfloat16* __restrict__ Ahi, const __nv_bfloat16* __restrict__ Alo,
                     const __nv_bfloat16* __restrict__ Bhi, const __nv_bfloat16* __restrict__ Blo,
                     float* __restrict__ C, int M, int K, int N) {
    extern __shared__ __align__(1024) char smem[];
    uint32_t sbase = smem_to_u32(smem);
    int tid = threadIdx.x, wid = tid >> 5, lid = tid & 31;
    int mwarp = wid & 3, nwarp = wid >> 2;
    int row0 = blockIdx.y * 128;
    int col0 = blockIdx.x * 64;

    float acc[2][4][4];
#pragma unroll
    for (int mt = 0; mt < 2; mt++)
#pragma unroll
        for (int nt = 0; nt < 4; nt++)
#pragma unroll
            for (int q = 0; q < 4; q++) acc[mt][nt][q] = 0.0f;

    const int nchunks = K >> 6;

    issue_stage(Ahi, Alo, Bhi, Blo, sbase, 0, 0, row0, col0, M, K, tid);
    issue_stage(Ahi, Alo, Bhi, Blo, sbase, 1, 1, row0, col0, M, K, tid);

    int raA = mwarp * 32 + (lid & 15);
    int caA = lid >> 4;
    int rbB = nwarp * 32 + ((lid >> 4) << 3) + (lid & 7);
    int cbB = (lid >> 3) & 1;

    for (int kc = 0; kc < nchunks; kc++) {
        CP_WAIT1();
        __syncthreads();
        int stage = kc & 1;
        uint32_t aB = sbase + stage * STAGE_BYTES;
        uint32_t bB = aB + 32768;

#pragma unroll
        for (int k16 = 0; k16 < 4; k16++) {
            uint32_t ah[2][4], al[2][4];
#pragma unroll
            for (int mt = 0; mt < 2; mt++) {
                int r = raA + mt * 16;
                int c = caA + k16 * 2;
                uint32_t off = r * 128 + (((c ^ (r & 7)) << 4));
                LDSM_X4(ah[mt][0], ah[mt][1], ah[mt][2], ah[mt][3], aB + off);
                LDSM_X4(al[mt][0], al[mt][1], al[mt][2], al[mt][3], aB + 16384 + off);
            }
            uint32_t bh[4][2], bl[4][2];
#pragma unroll
            for (int ntp = 0; ntp < 2; ntp++) {
                int r = rbB + ntp * 16;
                int c = cbB + k16 * 2;
                uint32_t off = r * 128 + (((c ^ (r & 7)) << 4));
                LDSM_X4(bh[2 * ntp][0], bh[2 * ntp][1], bh[2 * ntp + 1][0], bh[2 * ntp + 1][1], bB + off);
                LDSM_X4(bl[2 * ntp][0], bl[2 * ntp][1], bl[2 * ntp + 1][0], bl[2 * ntp + 1][1], bB + 8192 + off);
            }
#pragma unroll
            for (int mt = 0; mt < 2; mt++)
#pragma unroll
                for (int nt = 0; nt < 4; nt++) {
                    MMA_BF16(acc[mt][nt], ah[mt], bh[nt]);
                    MMA_BF16(acc[mt][nt], ah[mt], bl[nt]);
                    MMA_BF16(acc[mt][nt], al[mt], bh[nt]);
                }
        }
        __syncthreads();
        if (kc + 2 < nchunks)
            issue_stage(Ahi, Alo, Bhi, Blo, sbase, stage, kc + 2, row0, col0, M, K, tid);
    }

    int g = lid >> 2, t2 = (lid & 3) * 2;
#pragma unroll
    for (int mt = 0; mt < 2; mt++) {
        int r0g = row0 + mwarp * 32 + mt * 16 + g;
#pragma unroll
        for (int nt = 0; nt < 4; nt++) {
            int cn = col0 + nwarp * 32 + nt * 8 + t2;
            if (r0g < M)
                *reinterpret_cast<float2*>(&C[(size_t)r0g * N + cn]) =
                    make_float2(acc[mt][nt][0], acc[mt][nt][1]);
            if (r0g + 8 < M)
                *reinterpret_cast<float2*>(&C[(size_t)(r0g + 8) * N + cn]) =
                    make_float2(acc[mt][nt][2], acc[mt][nt][3]);
        }
    }
}

// ---------------- SPMM + bias (+ReLU); NVEC = D/4; 128/NVEC nodes per 128-thread block ----------------
template <int NVEC>
__global__ void spmm_kernel(const float* __restrict__ tmp, const int* __restrict__ cnt,
                            const int2* __restrict__ bpack,
                            const float* __restrict__ bias,
                            float* __restrict__ outf,
                            __nv_bfloat16* __restrict__ oh, __nv_bfloat16* __restrict__ ol,
                            int do_relu, int split) {
    constexpr int NPB = 128 / NVEC;
    int sub = threadIdx.x / NVEC;
    int c = threadIdx.x % NVEC;
    int node = blockIdx.x * NPB + sub;
    if (node >= NN) return;
    int deg = __ldg(&cnt[node]);
    if (deg > CAP) deg = CAP;
    const float4* t4 = reinterpret_cast<const float4*>(tmp);
    const float4* b4 = reinterpret_cast<const float4*>(bias);
    const int2* __restrict__ bp = &bpack[node * CAP];

    float4 acc = make_float4(0.f, 0.f, 0.f, 0.f);
#pragma unroll 4
    for (int e = 0; e < deg; e++) {
        int2 pw = __ldg(&bp[e]);
        float w = __int_as_float(pw.y);
        float4 v = __ldg(&t4[(size_t)pw.x * NVEC + c]);
        acc.x = fmaf(w, v.x, acc.x);
        acc.y = fmaf(w, v.y, acc.y);
        acc.z = fmaf(w, v.z, acc.z);
        acc.w = fmaf(w, v.w, acc.w);
    }
    float4 bb = __ldg(&b4[c]);
    acc.x += bb.x; acc.y += bb.y; acc.z += bb.z; acc.w += bb.w;
    if (do_relu) {
        acc.x = fmaxf(acc.x, 0.f); acc.y = fmaxf(acc.y, 0.f);
        acc.z = fmaxf(acc.z, 0.f); acc.w = fmaxf(acc.w, 0.f);
    }
    size_t o4 = (size_t)node * NVEC + c;
    if (split) {
        __nv_bfloat16 hx = __float2bfloat16(acc.x), hy = __float2bfloat16(acc.y);
        __nv_bfloat16 hz = __float2bfloat16(acc.z), hw = __float2bfloat16(acc.w);
        float lx = acc.x - __bfloat162float(hx), ly = acc.y - __bfloat162float(hy);
        float lz = acc.z - __bfloat162float(hz), lw = acc.w - __bfloat162float(hw);
        __nv_bfloat162 h0 = __nv_bfloat162(hx, hy), h1 = __nv_bfloat162(hz, hw);
        __nv_bfloat162 l0 = __nv_bfloat162(__float2bfloat16(lx), __float2bfloat16(ly));
        __nv_bfloat162 l1 = __nv_bfloat162(__float2bfloat16(lz), __float2bfloat16(lw));
        uint2 ph, pl;
        ph.x = *reinterpret_cast<uint32_t*>(&h0); ph.y = *reinterpret_cast<uint32_t*>(&h1);
        pl.x = *reinterpret_cast<uint32_t*>(&l0); pl.y = *reinterpret_cast<uint32_t*>(&l1);
        reinterpret_cast<uint2*>(oh)[o4] = ph;
        reinterpret_cast<uint2*>(ol)[o4] = pl;
    } else {
        reinterpret_cast<float4*>(outf)[o4] = acc;
    }
}

// ---------------- launch ----------------
extern "C" void kernel_launch(void* const* d_in, const int* in_sizes, int n_in,
                              void* d_out, int out_size) {
    const float* x    = (const float*)d_in[0];
    const int*   esrc = (const int*)d_in[1];
    const int*   edst = (const int*)d_in[2];
    const float* ew   = (const float*)d_in[3];
    const float* W1 = (const float*)d_in[4];  const float* b1 = (const float*)d_in[5];
    const float* W2 = (const float*)d_in[6];  const float* b2 = (const float*)d_in[7];
    const float* W3 = (const float*)d_in[8];  const float* b3 = (const float*)d_in[9];
    const float* W4 = (const float*)d_in[10]; const float* b4 = (const float*)d_in[11];
    float* out = (float*)d_out;

    float* tmp;
    __nv_bfloat16 *ahi, *alo, *bthi, *btlo;
    int *cnt, *beid;
    int2* bpack;
    cudaGetSymbolAddress((void**)&tmp,   g_tmp);
    cudaGetSymbolAddress((void**)&ahi,   g_ahi);
    cudaGetSymbolAddress((void**)&alo,   g_alo);
    cudaGetSymbolAddress((void**)&cnt,   g_cnt);
    cudaGetSymbolAddress((void**)&bpack, g_bpack);
    cudaGetSymbolAddress((void**)&beid,  g_beid);
    cudaGetSymbolAddress((void**)&bthi,  g_bthi);
    cudaGetSymbolAddress((void**)&btlo,  g_btlo);

    const int SMEM = 2 * STAGE_BYTES;   // 98304
    cudaFuncSetAttribute(gemm_mma_kernel, cudaFuncAttributeMaxDynamicSharedMemorySize, SMEM);

    cudaStream_t B = g_side.s;

    // ---- fork: convW + edge bucketing + canonical ordering on side stream B ----
    cudaEventRecord(g_side.fork, 0);
    cudaStreamWaitEvent(B, g_side.fork, 0);
    convW_all_kernel<<<dim3(16 * 16, 1, 4), dim3(32, 8), 0, B>>>(W1, W2, W3, W4, bthi, btlo);
    cudaEventRecord(g_side.evW, B);
    zero_cnt_kernel<<<(NN + 255) / 256, 256, 0, B>>>(cnt, NN);
    scatter_edges_kernel<<<(NE + 255) / 256, 256, 0, B>>>(esrc, edst, ew, cnt, bpack, beid);
    sort_buckets_kernel<<<NN, CAP, 0, B>>>(cnt, bpack, beid);
    cudaEventRecord(g_side.bk, B);

    // ---- main stream M: x split, then serialized GEMM/SPMM chain ----
    conv_hilo_kernel<<<(NN * 128 + 255) / 256, 256>>>((const float4*)x, (uint2*)ahi, (uint2*)alo, NN * 128);
    cudaStreamWaitEvent(0, g_side.evW, 0);     // weights ready

    // Layer 1: 512 -> 512
    gemm_mma_kernel<<<dim3(8, 391), 256, SMEM>>>(ahi, alo, bthi, btlo, tmp, NN, 512, 512);
    cudaStreamWaitEvent(0, g_side.bk, 0);      // canonical buckets ready
    spmm_kernel<128><<<NN, 128>>>(tmp, cnt, bpack, b1, nullptr, ahi, alo, 1, 1);

    // Layer 2: 512 -> 256
    gemm_mma_kernel<<<dim3(4, 391), 256, SMEM>>>(ahi, alo, bthi + 262144, btlo + 262144, tmp, NN, 512, 256);
    spmm_kernel<64><<<(NN + 1) / 2, 128>>>(tmp, cnt, bpack, b2, nullptr, ahi, alo, 1, 1);

    // Layer 3: 256 -> 128
    gemm_mma_kernel<<<dim3(2, 391), 256, SMEM>>>(ahi, alo, bthi + 393216, btlo + 393216, tmp, NN, 256, 128);
    spmm_kernel<32><<<(NN + 3) / 4, 128>>>(tmp, cnt, bpack, b3, nullptr, ahi, alo, 1, 1);

    // Layer 4: 128 -> 64 (no ReLU, fp32 out)
    gemm_mma_kernel<<<dim3(1, 391), 256, SMEM>>>(ahi, alo, bthi + 425984, btlo + 425984, tmp, NN, 128, 64);
    spmm_kernel<16><<<(NN + 7) / 8, 128>>>(tmp, cnt, bpack, b4, out, nullptr, nullptr, 0, 0);

    (void)in_sizes; (void)n_in; (void)out_size;
}

// round 15
// speedup vs baseline: 1.2018x; 1.1924x over previous
#include <cuda_runtime.h>
#include <cuda_bf16.h>
#include <cuda_fp16.h>
#include <cstdint>

#define NN 50000
#define NE 800000
#define CAP 64

// ---------------- scratch (device globals: no allocation) ----------------
__device__ __align__(16) __half         g_tmp[NN * 512];   // GEMM output (pre-agg), fp16
__device__ __align__(16) __nv_bfloat16  g_ahi[NN * 512];   // activation hi split
__device__ __align__(16) __nv_bfloat16  g_alo[NN * 512];   // activation lo split
__device__ int            g_cnt[NN];
__device__ __align__(16) int2 g_bpack[NN * CAP];           // packed (src, weight-bits) per slot
__device__ int            g_beid[NN * CAP];                // edge id per slot (canonical order)
// transposed weights (bf16 hi/lo), [N,K] layout, packed:
// L1 off 0 (512*512), L2 off 262144 (256*512), L3 off 393216 (128*256), L4 off 425984 (64*128)
__device__ __align__(16) __nv_bfloat16  g_bthi[434176];
__device__ __align__(16) __nv_bfloat16  g_btlo[434176];

// ---------------- side stream + events (created pre-main) ----------------
struct SideRes {
    cudaStream_t s;
    cudaEvent_t fork, evW, bk;
    SideRes() {
        cudaStreamCreate(&s);
        cudaEventCreateWithFlags(&fork, cudaEventDisableTiming);
        cudaEventCreateWithFlags(&evW,  cudaEventDisableTiming);
        cudaEventCreateWithFlags(&bk,   cudaEventDisableTiming);
    }
};
static SideRes g_side;

// ---------------- PTX helpers (baseline sm_80+ PTX only) ----------------
__device__ __forceinline__ uint32_t smem_to_u32(const void* p) {
    uint32_t a;
    asm("{ .reg .u64 t; cvta.to.shared.u64 t, %1; cvt.u32.u64 %0, t; }" : "=r"(a) : "l"(p));
    return a;
}

#define CP_ASYNC16(dst, src) \
    asm volatile("cp.async.cg.shared.global [%0], [%1], 16;" :: "r"(dst), "l"(src) : "memory")
#define CP_COMMIT() asm volatile("cp.async.commit_group;" ::: "memory")
#define CP_WAIT1()  asm volatile("cp.async.wait_group 1;" ::: "memory")

#define LDSM_X4(r0, r1, r2, r3, addr) \
    asm volatile("ldmatrix.sync.aligned.m8n8.x4.shared.b16 {%0,%1,%2,%3}, [%4];" \
                 : "=r"(r0), "=r"(r1), "=r"(r2), "=r"(r3) : "r"(addr))

#define MMA_BF16(d, a, b) \
    asm volatile("mma.sync.aligned.m16n8k16.row.col.f32.bf16.bf16.f32 " \
                 "{%0,%1,%2,%3}, {%4,%5,%6,%7}, {%8,%9}, {%0,%1,%2,%3};" \
                 : "+f"((d)[0]), "+f"((d)[1]), "+f"((d)[2]), "+f"((d)[3]) \
                 : "r"((a)[0]), "r"((a)[1]), "r"((a)[2]), "r"((a)[3]), \
                   "r"((b)[0]), "r"((b)[1]))

// ---------------- prep kernels ----------------
__global__ void zero_cnt_kernel(int* cnt, int n) {
    int i = blockIdx.x * blockDim.x + threadIdx.x;
    if (i < n) cnt[i] = 0;
}

__global__ void scatter_edges_kernel(const int* __restrict__ esrc, const int* __restrict__ edst,
                                     const float* __restrict__ ew, int* __restrict__ cnt,
                                     int2* __restrict__ bpack, int* __restrict__ beid) {
    int e = blockIdx.x * blockDim.x + threadIdx.x;
    if (e >= NE) return;
    int d = edst[e];
    int p = atomicAdd(&cnt[d], 1);
    if (p < CAP) {
        float w = ew[e];
        bpack[d * CAP + p] = make_int2(esrc[e], __float_as_int(w));
        beid[d * CAP + p]  = e;
    }
}

// Canonicalize bucket order: rank-sort each node's bucket by edge id.
__global__ void sort_buckets_kernel(const int* __restrict__ cnt, int2* __restrict__ bpack,
                                    const int* __restrict__ beid) {
    __shared__ int  se[CAP];
    __shared__ int2 sp[CAP];
    int node = blockIdx.x;
    int deg = cnt[node];
    if (deg > CAP) deg = CAP;
    int t = threadIdx.x;
    if (t < deg) {
        se[t] = beid[node * CAP + t];
        sp[t] = bpack[node * CAP + t];
    }
    __syncthreads();
    if (t < deg) {
        int my = se[t];
        int r = 0;
        for (int j = 0; j < deg; j++) r += (se[j] < my);
        bpack[node * CAP + r] = sp[t];
    }
}

// fp32 -> bf16 hi/lo split (vectorized by 4)
__global__ void conv_hilo_kernel(const float4* __restrict__ in, uint2* __restrict__ oh,
                                 uint2* __restrict__ ol, int n4) {
    int i = blockIdx.x * blockDim.x + threadIdx.x;
    if (i >= n4) return;
    float4 v = in[i];
    __nv_bfloat16 hx = __float2bfloat16(v.x), hy = __float2bfloat16(v.y);
    __nv_bfloat16 hz = __float2bfloat16(v.z), hw = __float2bfloat16(v.w);
    float lx = v.x - __bfloat162float(hx), ly = v.y - __bfloat162float(hy);
    float lz = v.z - __bfloat162float(hz), lw = v.w - __bfloat162float(hw);
    __nv_bfloat162 h0 = __nv_bfloat162(hx, hy), h1 = __nv_bfloat162(hz, hw);
    __nv_bfloat162 l0 = __nv_bfloat162(__float2bfloat16(lx), __float2bfloat16(ly));
    __nv_bfloat162 l1 = __nv_bfloat162(__float2bfloat16(lz), __float2bfloat16(lw));
    uint2 ph, pl;
    ph.x = *reinterpret_cast<uint32_t*>(&h0); ph.y = *reinterpret_cast<uint32_t*>(&h1);
    pl.x = *reinterpret_cast<uint32_t*>(&l0); pl.y = *reinterpret_cast<uint32_t*>(&l1);
    oh[i] = ph; ol[i] = pl;
}

// All four W [K,N] fp32 -> Bt_hi/Bt_lo [N,K] bf16, one launch.
__global__ void convW_all_kernel(const float* __restrict__ W1, const float* __restrict__ W2,
                                 const float* __restrict__ W3, const float* __restrict__ W4,
                                 __nv_bfloat16* __restrict__ oh, __nv_bfloat16* __restrict__ ol) {
    __shared__ float t[32][33];
    int layer = blockIdx.z;
    const float* W; int K, N, off;
    if (layer == 0)      { W = W1; K = 512; N = 512; off = 0; }
    else if (layer == 1) { W = W2; K = 512; N = 256; off = 262144; }
    else if (layer == 2) { W = W3; K = 256; N = 128; off = 393216; }
    else                 { W = W4; K = 128; N = 64;  off = 425984; }
    int nbx = N >> 5;
    if ((int)blockIdx.x >= nbx * (K >> 5)) return;
    int n0 = (blockIdx.x % nbx) * 32;
    int k0 = (blockIdx.x / nbx) * 32;
    int tx = threadIdx.x, ty = threadIdx.y;   // block (32,8)
#pragma unroll
    for (int i = 0; i < 4; i++)
        t[ty + i * 8][tx] = W[(long long)(k0 + ty + i * 8) * N + n0 + tx];
    __syncthreads();
#pragma unroll
    for (int i = 0; i < 4; i++) {
        float v = t[tx][ty + i * 8];
        __nv_bfloat16 h = __float2bfloat16(v);
        float l = v - __bfloat162float(h);
        long long o = off + (long long)(n0 + ty + i * 8) * K + k0 + tx;
        oh[o] = h;
        ol[o] = __float2bfloat16(l);
    }
}

// ---------------- mma.sync split-bf16 GEMM (R4-proven shape): C[M,N] = A @ Bt^T, fp16 out ----------------
// CTA: 128(M) x 64(N), 256 threads; K chunks of 64, cp.async double-buffered.
#define STAGE_BYTES 49152

__device__ __forceinline__ void issue_stage(
    const __nv_bfloat16* Ahi, const __nv_bfloat16* Alo,
    const __nv_bfloat16* Bhi, const __nv_bfloat16* Blo,
    uint32_t sbase, int stage, int kc, int row0, int col0, int M, int K, int tid) {
    int k0 = kc << 6;
    uint32_t sA = sbase + stage * STAGE_BYTES;
    uint32_t sB = sA + 32768;
#pragma unroll
    for (int i = 0; i < 8; i++) {               // A: 2048 x 16B
        int f = tid + i * 256;
        int split = f >> 10, r = (f >> 3) & 127, c = f & 7;
        int gr = row0 + r; if (gr >= M) gr = M - 1;
        const __nv_bfloat16* src = (split ? Alo : Ahi) + (size_t)gr * K + k0 + c * 8;
        uint32_t dst = sA + split * 16384 + r * 128 + (((c ^ (r & 7)) << 4));
        CP_ASYNC16(dst, src);
    }
#pragma unroll
    for (int i = 0; i < 4; i++) {               // B: 1024 x 16B
        int f = tid + i * 256;
        int split = f >> 9, r = (f >> 3) & 63, c = f & 7;
        int gn = col0 + r;
        const __nv_bfloat16* src = (split ? Blo : Bhi) + (size_t)gn * K + k0 + c * 8;
        uint32_t dst = sB + split * 8192 + r * 128 + (((c ^ (r & 7)) << 4));
        CP_ASYNC16(dst, src);
    }
    CP_COMMIT();
}

__global__ __launch_bounds__(256, 2)
void gemm_mma_kernel(const __nv_bfloat16* __restrict__ Ahi, const __nv_bfloat16* __restrict__ Alo,
                     const __nv_bfloat16* __restrict__ Bhi, const __nv_bfloat16* __restrict__ Blo,
                     __half* __restrict__ C, int M, int K, int N) {
    extern __shared__ __align__(1024) char smem[];
    uint32_t sbase = smem_to_u32(smem);
    int tid = threadIdx.x, wid = tid >> 5, lid = tid & 31;
    int mwarp = wid & 3, nwarp = wid >> 2;
    int row0 = blockIdx.y * 128;
    int col0 = blockIdx.x * 64;

    float acc[2][4][4];
#pragma unroll
    for (int mt = 0; mt < 2; mt++)
#pragma unroll
        for (int nt = 0; nt < 4; nt++)
#pragma unroll
            for (int q = 0; q < 4; q++) acc[mt][nt][q] = 0.0f;

    const int nchunks = K >> 6;

    issue_stage(Ahi, Alo, Bhi, Blo, sbase, 0, 0, row0, col0, M, K, tid);
    issue_stage(Ahi, Alo, Bhi, Blo, sbase, 1, 1, row0, col0, M, K, tid);

    int raA = mwarp * 32 + (lid & 15);
    int caA = lid >> 4;
    int rbB = nwarp * 32 + ((lid >> 4) << 3) + (lid & 7);
    int cbB = (lid >> 3) & 1;

    for (int kc = 0; kc < nchunks; kc++) {
        CP_WAIT1();
        __syncthreads();
        int stage = kc & 1;
        uint32_t aB = sbase + stage * STAGE_BYTES;
        uint32_t bB = aB + 32768;

#pragma unroll
        for (int k16 = 0; k16 < 4; k16++) {
            uint32_t ah[2][4], al[2][4];
#pragma unroll
            for (int mt = 0; mt < 2; mt++) {
                int r = raA + mt * 16;
                int c = caA + k16 * 2;
                uint32_t off = r * 128 + (((c ^ (r & 7)) << 4));
                LDSM_X4(ah[mt][0], ah[mt][1], ah[mt][2], ah[mt][3], aB + off);
                LDSM_X4(al[mt][0], al[mt][1], al[mt][2], al[mt][3], aB + 16384 + off);
            }
            uint32_t bh[4][2], bl[4][2];
#pragma unroll
            for (int ntp = 0; ntp < 2; ntp++) {
                int r = rbB + ntp * 16;
                int c = cbB + k16 * 2;
                uint32_t off = r * 128 + (((c ^ (r & 7)) << 4));
                LDSM_X4(bh[2 * ntp][0], bh[2 * ntp][1], bh[2 * ntp + 1][0], bh[2 * ntp + 1][1], bB + off);
                LDSM_X4(bl[2 * ntp][0], bl[2 * ntp][1], bl[2 * ntp + 1][0], bl[2 * ntp + 1][1], bB + 8192 + off);
            }
#pragma unroll
            for (int mt = 0; mt < 2; mt++)
#pragma unroll
                for (int nt = 0; nt < 4; nt++) {
                    MMA_BF16(acc[mt][nt], ah[mt], bh[nt]);
                    MMA_BF16(acc[mt][nt], ah[mt], bl[nt]);
                    MMA_BF16(acc[mt][nt], al[mt], bh[nt]);
                }
        }
        __syncthreads();
        if (kc + 2 < nchunks)
            issue_stage(Ahi, Alo, Bhi, Blo, sbase, stage, kc + 2, row0, col0, M, K, tid);
    }

    // epilogue: fp16 stores (half2 = 2 cols = 4B)
    int g = lid >> 2, t2 = (lid & 3) * 2;
#pragma unroll
    for (int mt = 0; mt < 2; mt++) {
        int r0g = row0 + mwarp * 32 + mt * 16 + g;
#pragma unroll
        for (int nt = 0; nt < 4; nt++) {
            int cn = col0 + nwarp * 32 + nt * 8 + t2;
            if (r0g < M)
                *reinterpret_cast<__half2*>(&C[(size_t)r0g * N + cn]) =
                    __floats2half2_rn(acc[mt][nt][0], acc[mt][nt][1]);
            if (r0g + 8 < M)
                *reinterpret_cast<__half2*>(&C[(size_t)(r0g + 8) * N + cn]) =
                    __floats2half2_rn(acc[mt][nt][2], acc[mt][nt][3]);
        }
    }
}

// ---------------- SPMM (fp16 gather, fp32 accum) + bias (+ReLU) ----------------
template <int NVEC>   // NVEC = D/4
__global__ void spmm_kernel(const __half* __restrict__ tmp, const int* __restrict__ cnt,
                            const int2* __restrict__ bpack,
                            const float* __restrict__ bias,
                            float* __restrict__ outf,
                            __nv_bfloat16* __restrict__ oh, __nv_bfloat16* __restrict__ ol,
                            int do_relu, int split) {
    constexpr int NPB = 128 / NVEC;
    int sub = threadIdx.x / NVEC;
    int c = threadIdx.x % NVEC;
    int node = blockIdx.x * NPB + sub;
    if (node >= NN) return;
    int deg = __ldg(&cnt[node]);
    if (deg > CAP) deg = CAP;
    const uint2* t4 = reinterpret_cast<const uint2*>(tmp);   // 4 halves per uint2
    const float4* b4 = reinterpret_cast<const float4*>(bias);
    const int2* __restrict__ bp = &bpack[node * CAP];

    float4 acc = make_float4(0.f, 0.f, 0.f, 0.f);
#pragma unroll 4
    for (int e = 0; e < deg; e++) {
        int2 pw = __ldg(&bp[e]);
        float w = __int_as_float(pw.y);
        uint2 pv = __ldg(&t4[(size_t)pw.x * NVEC + c]);
        __half2 h0 = *reinterpret_cast<__half2*>(&pv.x);
        __half2 h1 = *reinterpret_cast<__half2*>(&pv.y);
        float2 f0 = __half22float2(h0);
        float2 f1 = __half22float2(h1);
        acc.x = fmaf(w, f0.x, acc.x);
        acc.y = fmaf(w, f0.y, acc.y);
        acc.z = fmaf(w, f1.x, acc.z);
        acc.w = fmaf(w, f1.y, acc.w);
    }
    float4 bb = __ldg(&b4[c]);
    acc.x += bb.x; acc.y += bb.y; acc.z += bb.z; acc.w += bb.w;
    if (do_relu) {
        acc.x = fmaxf(acc.x, 0.f); acc.y = fmaxf(acc.y, 0.f);
        acc.z = fmaxf(acc.z, 0.f); acc.w = fmaxf(acc.w, 0.f);
    }
    size_t o4 = (size_t)node * NVEC + c;
    if (split) {
        __nv_bfloat16 hx = __float2bfloat16(acc.x), hy = __float2bfloat16(acc.y);
        __nv_bfloat16 hz = __float2bfloat16(acc.z), hw = __float2bfloat16(acc.w);
        float lx = acc.x - __bfloat162float(hx), ly = acc.y - __bfloat162float(hy);
        float lz = acc.z - __bfloat162float(hz), lw = acc.w - __bfloat162float(hw);
        __nv_bfloat162 h0 = __nv_bfloat162(hx, hy), h1 = __nv_bfloat162(hz, hw);
        __nv_bfloat162 l0 = __nv_bfloat162(__float2bfloat16(lx), __float2bfloat16(ly));
        __nv_bfloat162 l1 = __nv_bfloat162(__float2bfloat16(lz), __float2bfloat16(lw));
        uint2 ph, pl;
        ph.x = *reinterpret_cast<uint32_t*>(&h0); ph.y = *reinterpret_cast<uint32_t*>(&h1);
        pl.x = *reinterpret_cast<uint32_t*>(&l0); pl.y = *reinterpret_cast<uint32_t*>(&l1);
        reinterpret_cast<uint2*>(oh)[o4] = ph;
        reinterpret_cast<uint2*>(ol)[o4] = pl;
    } else {
        reinterpret_cast<float4*>(outf)[o4] = acc;
    }
}

// ---------------- launch ----------------
extern "C" void kernel_launch(void* const* d_in, const int* in_sizes, int n_in,
                              void* d_out, int out_size) {
    const float* x    = (const float*)d_in[0];
    const int*   esrc = (const int*)d_in[1];
    const int*   edst = (const int*)d_in[2];
    const float* ew   = (const float*)d_in[3];
    const float* W1 = (const float*)d_in[4];  const float* b1 = (const float*)d_in[5];
    const float* W2 = (const float*)d_in[6];  const float* b2 = (const float*)d_in[7];
    const float* W3 = (const float*)d_in[8];  const float* b3 = (const float*)d_in[9];
    const float* W4 = (const float*)d_in[10]; const float* b4 = (const float*)d_in[11];
    float* out = (float*)d_out;

    __half* tmp;
    __nv_bfloat16 *ahi, *alo, *bthi, *btlo;
    int *cnt, *beid;
    int2* bpack;
    cudaGetSymbolAddress((void**)&tmp,   g_tmp);
    cudaGetSymbolAddress((void**)&ahi,   g_ahi);
    cudaGetSymbolAddress((void**)&alo,   g_alo);
    cudaGetSymbolAddress((void**)&cnt,   g_cnt);
    cudaGetSymbolAddress((void**)&bpack, g_bpack);
    cudaGetSymbolAddress((void**)&beid,  g_beid);
    cudaGetSymbolAddress((void**)&bthi,  g_bthi);
    cudaGetSymbolAddress((void**)&btlo,  g_btlo);

    const int SMEM = 2 * STAGE_BYTES;   // 98304
    cudaFuncSetAttribute(gemm_mma_kernel, cudaFuncAttributeMaxDynamicSharedMemorySize, SMEM);

    cudaStream_t B = g_side.s;

    // ---- fork: convW + edge bucketing + canonical ordering on side stream B ----
    cudaEventRecord(g_side.fork, 0);
    cudaStreamWaitEvent(B, g_side.fork, 0);
    convW_all_kernel<<<dim3(16 * 16, 1, 4), dim3(32, 8), 0, B>>>(W1, W2, W3, W4, bthi, btlo);
    cudaEventRecord(g_side.evW, B);
    zero_cnt_kernel<<<(NN + 255) / 256, 256, 0, B>>>(cnt, NN);
    scatter_edges_kernel<<<(NE + 255) / 256, 256, 0, B>>>(esrc, edst, ew, cnt, bpack, beid);
    sort_buckets_kernel<<<NN, CAP, 0, B>>>(cnt, bpack, beid);
    cudaEventRecord(g_side.bk, B);

    // ---- main stream M: x split, then serialized GEMM/SPMM chain ----
    conv_hilo_kernel<<<(NN * 128 + 255) / 256, 256>>>((const float4*)x, (uint2*)ahi, (uint2*)alo, NN * 128);
    cudaStreamWaitEvent(0, g_side.evW, 0);     // weights ready

    // Layer 1: 512 -> 512
    gemm_mma_kernel<<<dim3(8, 391), 256, SMEM>>>(ahi, alo, bthi, btlo, tmp, NN, 512, 512);
    cudaStreamWaitEvent(0, g_side.bk, 0);      // canonical buckets ready
    spmm_kernel<128><<<NN, 128>>>(tmp, cnt, bpack, b1, nullptr, ahi, alo, 1, 1);

    // Layer 2: 512 -> 256
    gemm_mma_kernel<<<dim3(4, 391), 256, SMEM>>>(ahi, alo, bthi + 262144, btlo + 262144, tmp, NN, 512, 256);
    spmm_kernel<64><<<(NN + 1) / 2, 128>>>(tmp, cnt, bpack, b2, nullptr, ahi, alo, 1, 1);

    // Layer 3: 256 -> 128
    gemm_mma_kernel<<<dim3(2, 391), 256, SMEM>>>(ahi, alo, bthi + 393216, btlo + 393216, tmp, NN, 256, 128);
    spmm_kernel<32><<<(NN + 3) / 4, 128>>>(tmp, cnt, bpack, b3, nullptr, ahi, alo, 1, 1);

    // Layer 4: 128 -> 64 (no ReLU, fp32 out)
    gemm_mma_kernel<<<dim3(1, 391), 256, SMEM>>>(ahi, alo, bthi + 425984, btlo + 425984, tmp, NN, 128, 64);
    spmm_kernel<16><<<(NN + 7) / 8, 128>>>(tmp, cnt, bpack, b4, out, nullptr, nullptr, 0, 0);

    (void)in_sizes; (void)n_in; (void)out_size;
}

// round 16
// speedup vs baseline: 1.4459x; 1.2031x over previous
#include <cuda_runtime.h>
#include <cuda_bf16.h>
#include <cuda_fp16.h>
#include <cstdint>

#define NN 50000
#define NE 800000
#define CAP 64

// ---------------- scratch (device globals: no allocation) ----------------
__device__ __align__(16) __half g_tmp[NN * 512];   // GEMM output (pre-agg), fp16
__device__ __align__(16) __half g_act[NN * 512];   // activations, fp16 (single)
__device__ int            g_cnt[NN];
__device__ __align__(16) int2 g_bpack[NN * CAP];   // packed (src, weight-bits) per slot
__device__ int            g_beid[NN * CAP];        // edge id per slot (canonical order)
// transposed weights (fp16 hi/lo), [N,K] layout, packed:
// L1 off 0 (512*512), L2 off 262144 (256*512), L3 off 393216 (128*256), L4 off 425984 (64*128)
__device__ __align__(16) __half g_bthi[434176];
__device__ __align__(16) __half g_btlo[434176];

// ---------------- side stream + events (created pre-main) ----------------
struct SideRes {
    cudaStream_t s;
    cudaEvent_t fork, evW, bk;
    SideRes() {
        cudaStreamCreate(&s);
        cudaEventCreateWithFlags(&fork, cudaEventDisableTiming);
        cudaEventCreateWithFlags(&evW,  cudaEventDisableTiming);
        cudaEventCreateWithFlags(&bk,   cudaEventDisableTiming);
    }
};
static SideRes g_side;

// ---------------- PTX helpers (baseline sm_80+ PTX only) ----------------
__device__ __forceinline__ uint32_t smem_to_u32(const void* p) {
    uint32_t a;
    asm("{ .reg .u64 t; cvta.to.shared.u64 t, %1; cvt.u32.u64 %0, t; }" : "=r"(a) : "l"(p));
    return a;
}

#define CP_ASYNC16(dst, src) \
    asm volatile("cp.async.cg.shared.global [%0], [%1], 16;" :: "r"(dst), "l"(src) : "memory")
#define CP_COMMIT() asm volatile("cp.async.commit_group;" ::: "memory")
#define CP_WAIT1()  asm volatile("cp.async.wait_group 1;" ::: "memory")

#define LDSM_X4(r0, r1, r2, r3, addr) \
    asm volatile("ldmatrix.sync.aligned.m8n8.x4.shared.b16 {%0,%1,%2,%3}, [%4];" \
                 : "=r"(r0), "=r"(r1), "=r"(r2), "=r"(r3) : "r"(addr))

#define MMA_F16(d, a, b) \
    asm volatile("mma.sync.aligned.m16n8k16.row.col.f32.f16.f16.f32 " \
                 "{%0,%1,%2,%3}, {%4,%5,%6,%7}, {%8,%9}, {%0,%1,%2,%3};" \
                 : "+f"((d)[0]), "+f"((d)[1]), "+f"((d)[2]), "+f"((d)[3]) \
                 : "r"((a)[0]), "r"((a)[1]), "r"((a)[2]), "r"((a)[3]), \
                   "r"((b)[0]), "r"((b)[1]))

// ---------------- prep kernels ----------------
__global__ void zero_cnt_kernel(int* cnt, int n) {
    int i = blockIdx.x * blockDim.x + threadIdx.x;
    if (i < n) cnt[i] = 0;
}

__global__ void scatter_edges_kernel(const int* __restrict__ esrc, const int* __restrict__ edst,
                                     const float* __restrict__ ew, int* __restrict__ cnt,
                                     int2* __restrict__ bpack, int* __restrict__ beid) {
    int e = blockIdx.x * blockDim.x + threadIdx.x;
    if (e >= NE) return;
    int d = edst[e];
    int p = atomicAdd(&cnt[d], 1);
    if (p < CAP) {
        float w = ew[e];
        bpack[d * CAP + p] = make_int2(esrc[e], __float_as_int(w));
        beid[d * CAP + p]  = e;
    }
}

// Canonicalize bucket order: rank-sort each node's bucket by edge id.
__global__ void sort_buckets_kernel(const int* __restrict__ cnt, int2* __restrict__ bpack,
                                    const int* __restrict__ beid) {
    __shared__ int  se[CAP];
    __shared__ int2 sp[CAP];
    int node = blockIdx.x;
    int deg = cnt[node];
    if (deg > CAP) deg = CAP;
    int t = threadIdx.x;
    if (t < deg) {
        se[t] = beid[node * CAP + t];
        sp[t] = bpack[node * CAP + t];
    }
    __syncthreads();
    if (t < deg) {
        int my = se[t];
        int r = 0;
        for (int j = 0; j < deg; j++) r += (se[j] < my);
        bpack[node * CAP + r] = sp[t];
    }
}

// fp32 -> fp16 convert (x input), vectorized by 4
__global__ void conv_x_kernel(const float4* __restrict__ in, uint2* __restrict__ o, int n4) {
    int i = blockIdx.x * blockDim.x + threadIdx.x;
    if (i >= n4) return;
    float4 v = in[i];
    __half2 h0 = __floats2half2_rn(v.x, v.y);
    __half2 h1 = __floats2half2_rn(v.z, v.w);
    uint2 p;
    p.x = *reinterpret_cast<uint32_t*>(&h0);
    p.y = *reinterpret_cast<uint32_t*>(&h1);
    o[i] = p;
}

// All four W [K,N] fp32 -> Bt_hi/Bt_lo [N,K] fp16, one launch.
__global__ void convW_all_kernel(const float* __restrict__ W1, const float* __restrict__ W2,
                                 const float* __restrict__ W3, const float* __restrict__ W4,
                                 __half* __restrict__ oh, __half* __restrict__ ol) {
    __shared__ float t[32][33];
    int layer = blockIdx.z;
    const float* W; int K, N, off;
    if (layer == 0)      { W = W1; K = 512; N = 512; off = 0; }
    else if (layer == 1) { W = W2; K = 512; N = 256; off = 262144; }
    else if (layer == 2) { W = W3; K = 256; N = 128; off = 393216; }
    else                 { W = W4; K = 128; N = 64;  off = 425984; }
    int nbx = N >> 5;
    if ((int)blockIdx.x >= nbx * (K >> 5)) return;
    int n0 = (blockIdx.x % nbx) * 32;
    int k0 = (blockIdx.x / nbx) * 32;
    int tx = threadIdx.x, ty = threadIdx.y;   // block (32,8)
#pragma unroll
    for (int i = 0; i < 4; i++)
        t[ty + i * 8][tx] = W[(long long)(k0 + ty + i * 8) * N + n0 + tx];
    __syncthreads();
#pragma unroll
    for (int i = 0; i < 4; i++) {
        float v = t[tx][ty + i * 8];
        __half h = __float2half_rn(v);
        float l = v - __half2float(h);
        long long o = off + (long long)(n0 + ty + i * 8) * K + k0 + tx;
        oh[o] = h;
        ol[o] = __float2half_rn(l);
    }
}

// ---------------- mma.sync fp16 GEMM: C[M,N] = A @ (Bhi+Blo)^T, fp16 A single, fp16 out ----------------
// CTA: 128(M) x 64(N), 256 threads; K chunks of 64, cp.async double-buffered.
// Stage: A 128x64 fp16 = 16KB, B hi/lo 2 x 64x64 fp16 = 16KB -> 32KB; 2 stages = 64KB.
#define STAGE_BYTES 32768

__device__ __forceinline__ void issue_stage(
    const __half* A, const __half* Bhi, const __half* Blo,
    uint32_t sbase, int stage, int kc, int row0, int col0, int M, int K, int tid) {
    int k0 = kc << 6;
    uint32_t sA = sbase + stage * STAGE_BYTES;
    uint32_t sB = sA + 16384;
#pragma unroll
    for (int i = 0; i < 4; i++) {               // A: 1024 x 16B
        int f = tid + i * 256;
        int r = f >> 3, c = f & 7;
        int gr = row0 + r; if (gr >= M) gr = M - 1;
        const __half* src = A + (size_t)gr * K + k0 + c * 8;
        uint32_t dst = sA + r * 128 + (((c ^ (r & 7)) << 4));
        CP_ASYNC16(dst, src);
    }
#pragma unroll
    for (int i = 0; i < 4; i++) {               // B: 1024 x 16B (hi 512 + lo 512)
        int f = tid + i * 256;
        int split = f >> 9, r = (f >> 3) & 63, c = f & 7;
        int gn = col0 + r;
        const __half* src = (split ? Blo : Bhi) + (size_t)gn * K + k0 + c * 8;
        uint32_t dst = sB + split * 8192 + r * 128 + (((c ^ (r & 7)) << 4));
        CP_ASYNC16(dst, src);
    }
    CP_COMMIT();
}

__global__ __launch_bounds__(256, 2)
void gemm_mma_kernel(const __half* __restrict__ A,
                     const __half* __restrict__ Bhi, const __half* __restrict__ Blo,
                     __half* __restrict__ C, int M, int K, int N) {
    extern __shared__ __align__(1024) char smem[];
    uint32_t sbase = smem_to_u32(smem);
    int tid = threadIdx.x, wid = tid >> 5, lid = tid & 31;
    int mwarp = wid & 3, nwarp = wid >> 2;
    int row0 = blockIdx.y * 128;
    int col0 = blockIdx.x * 64;

    float acc[2][4][4];
#pragma unroll
    for (int mt = 0; mt < 2; mt++)
#pragma unroll
        for (int nt = 0; nt < 4; nt++)
#pragma unroll
            for (int q = 0; q < 4; q++) acc[mt][nt][q] = 0.0f;

    const int nchunks = K >> 6;

    issue_stage(A, Bhi, Blo, sbase, 0, 0, row0, col0, M, K, tid);
    issue_stage(A, Bhi, Blo, sbase, 1, 1, row0, col0, M, K, tid);

    int raA = mwarp * 32 + (lid & 15);                      // + mt*16
    int caA = lid >> 4;                                     // + k16*2
    int rbB = nwarp * 32 + ((lid >> 4) << 3) + (lid & 7);   // + ntp*16
    int cbB = (lid >> 3) & 1;                               // + k16*2

    for (int kc = 0; kc < nchunks; kc++) {
        CP_WAIT1();
        __syncthreads();
        int stage = kc & 1;
        uint32_t aB = sbase + stage * STAGE_BYTES;
        uint32_t bB = aB + 16384;

#pragma unroll
        for (int k16 = 0; k16 < 4; k16++) {
            uint32_t av[2][4];
#pragma unroll
            for (int mt = 0; mt < 2; mt++) {
                int r = raA + mt * 16;
                int c = caA + k16 * 2;
                uint32_t off = r * 128 + (((c ^ (r & 7)) << 4));
                LDSM_X4(av[mt][0], av[mt][1], av[mt][2], av[mt][3], aB + off);
            }
            uint32_t bh[4][2], bl[4][2];
#pragma unroll
            for (int ntp = 0; ntp < 2; ntp++) {
                int r = rbB + ntp * 16;
                int c = cbB + k16 * 2;
                uint32_t off = r * 128 + (((c ^ (r & 7)) << 4));
                LDSM_X4(bh[2 * ntp][0], bh[2 * ntp][1], bh[2 * ntp + 1][0], bh[2 * ntp + 1][1], bB + off);
                LDSM_X4(bl[2 * ntp][0], bl[2 * ntp][1], bl[2 * ntp + 1][0], bl[2 * ntp + 1][1], bB + 8192 + off);
            }
#pragma unroll
            for (int mt = 0; mt < 2; mt++)
#pragma unroll
                for (int nt = 0; nt < 4; nt++) {
                    MMA_F16(acc[mt][nt], av[mt], bh[nt]);
                    MMA_F16(acc[mt][nt], av[mt], bl[nt]);
                }
        }
        __syncthreads();
        if (kc + 2 < nchunks)
            issue_stage(A, Bhi, Blo, sbase, stage, kc + 2, row0, col0, M, K, tid);
    }

    // epilogue: fp16 stores (half2 = 2 cols = 4B)
    int g = lid >> 2, t2 = (lid & 3) * 2;
#pragma unroll
    for (int mt = 0; mt < 2; mt++) {
        int r0g = row0 + mwarp * 32 + mt * 16 + g;
#pragma unroll
        for (int nt = 0; nt < 4; nt++) {
            int cn = col0 + nwarp * 32 + nt * 8 + t2;
            if (r0g < M)
                *reinterpret_cast<__half2*>(&C[(size_t)r0g * N + cn]) =
                    __floats2half2_rn(acc[mt][nt][0], acc[mt][nt][1]);
            if (r0g + 8 < M)
                *reinterpret_cast<__half2*>(&C[(size_t)(r0g + 8) * N + cn]) =
                    __floats2half2_rn(acc[mt][nt][2], acc[mt][nt][3]);
        }
    }
}

// ---------------- SPMM (fp16 gather, fp32 accum) + bias (+ReLU); fp16 or fp32 out ----------------
template <int NVEC>   // NVEC = D/4
__global__ void spmm_kernel(const __half* __restrict__ tmp, const int* __restrict__ cnt,
                            const int2* __restrict__ bpack,
                            const float* __restrict__ bias,
                            float* __restrict__ outf,
                            __half* __restrict__ oa,
                            int do_relu, int split) {
    constexpr int NPB = 128 / NVEC;
    int sub = threadIdx.x / NVEC;
    int c = threadIdx.x % NVEC;
    int node = blockIdx.x * NPB + sub;
    if (node >= NN) return;
    int deg = __ldg(&cnt[node]);
    if (deg > CAP) deg = CAP;
    const uint2* t4 = reinterpret_cast<const uint2*>(tmp);   // 4 halves per uint2
    const float4* b4 = reinterpret_cast<const float4*>(bias);
    const int2* __restrict__ bp = &bpack[node * CAP];

    float4 acc = make_float4(0.f, 0.f, 0.f, 0.f);
#pragma unroll 4
    for (int e = 0; e < deg; e++) {
        int2 pw = __ldg(&bp[e]);
        float w = __int_as_float(pw.y);
        uint2 pv = __ldg(&t4[(size_t)pw.x * NVEC + c]);
        __half2 h0 = *reinterpret_cast<__half2*>(&pv.x);
        __half2 h1 = *reinterpret_cast<__half2*>(&pv.y);
        float2 f0 = __half22float2(h0);
        float2 f1 = __half22float2(h1);
        acc.x = fmaf(w, f0.x, acc.x);
        acc.y = fmaf(w, f0.y, acc.y);
        acc.z = fmaf(w, f1.x, acc.z);
        acc.w = fmaf(w, f1.y, acc.w);
    }
    float4 bb = __ldg(&b4[c]);
    acc.x += bb.x; acc.y += bb.y; acc.z += bb.z; acc.w += bb.w;
    if (do_relu) {
        acc.x = fmaxf(acc.x, 0.f); acc.y = fmaxf(acc.y, 0.f);
        acc.z = fmaxf(acc.z, 0.f); acc.w = fmaxf(acc.w, 0.f);
    }
    size_t o4 = (size_t)node * NVEC + c;
    if (split) {
        __half2 h0 = __floats2half2_rn(acc.x, acc.y);
        __half2 h1 = __floats2half2_rn(acc.z, acc.w);
        uint2 p;
        p.x = *reinterpret_cast<uint32_t*>(&h0);
        p.y = *reinterpret_cast<uint32_t*>(&h1);
        reinterpret_cast<uint2*>(oa)[o4] = p;
    } else {
        reinterpret_cast<float4*>(outf)[o4] = acc;
    }
}

// ---------------- launch ----------------
extern "C" void kernel_launch(void* const* d_in, const int* in_sizes, int n_in,
                              void* d_out, int out_size) {
    const float* x    = (const float*)d_in[0];
    const int*   esrc = (const int*)d_in[1];
    const int*   edst = (const int*)d_in[2];
    const float* ew   = (const float*)d_in[3];
    const float* W1 = (const float*)d_in[4];  const float* b1 = (const float*)d_in[5];
    const float* W2 = (const float*)d_in[6];  const float* b2 = (const float*)d_in[7];
    const float* W3 = (const float*)d_in[8];  const float* b3 = (const float*)d_in[9];
    const float* W4 = (const float*)d_in[10]; const float* b4 = (const float*)d_in[11];
    float* out = (float*)d_out;

    __half *tmp, *act, *bthi, *btlo;
    int *cnt, *beid;
    int2* bpack;
    cudaGetSymbolAddress((void**)&tmp,   g_tmp);
    cudaGetSymbolAddress((void**)&act,   g_act);
    cudaGetSymbolAddress((void**)&cnt,   g_cnt);
    cudaGetSymbolAddress((void**)&bpack, g_bpack);
    cudaGetSymbolAddress((void**)&beid,  g_beid);
    cudaGetSymbolAddress((void**)&bthi,  g_bthi);
    cudaGetSymbolAddress((void**)&btlo,  g_btlo);

    const int SMEM = 2 * STAGE_BYTES;   // 65536
    cudaFuncSetAttribute(gemm_mma_kernel, cudaFuncAttributeMaxDynamicSharedMemorySize, SMEM);

    cudaStream_t B = g_side.s;

    // ---- fork: convW + edge bucketing + canonical ordering on side stream B ----
    cudaEventRecord(g_side.fork, 0);
    cudaStreamWaitEvent(B, g_side.fork, 0);
    convW_all_kernel<<<dim3(16 * 16, 1, 4), dim3(32, 8), 0, B>>>(W1, W2, W3, W4, bthi, btlo);
    cudaEventRecord(g_side.evW, B);
    zero_cnt_kernel<<<(NN + 255) / 256, 256, 0, B>>>(cnt, NN);
    scatter_edges_kernel<<<(NE + 255) / 256, 256, 0, B>>>(esrc, edst, ew, cnt, bpack, beid);
    sort_buckets_kernel<<<NN, CAP, 0, B>>>(cnt, bpack, beid);
    cudaEventRecord(g_side.bk, B);

    // ---- main stream M: x -> fp16, then serialized GEMM/SPMM chain ----
    conv_x_kernel<<<(NN * 128 + 255) / 256, 256>>>((const float4*)x, (uint2*)act, NN * 128);
    cudaStreamWaitEvent(0, g_side.evW, 0);     // weights ready

    // Layer 1: 512 -> 512
    gemm_mma_kernel<<<dim3(8, 391), 256, SMEM>>>(act, bthi, btlo, tmp, NN, 512, 512);
    cudaStreamWaitEvent(0, g_side.bk, 0);      // canonical buckets ready
    spmm_kernel<128><<<NN, 128>>>(tmp, cnt, bpack, b1, nullptr, act, 1, 1);

    // Layer 2: 512 -> 256
    gemm_mma_kernel<<<dim3(4, 391), 256, SMEM>>>(act, bthi + 262144, btlo + 262144, tmp, NN, 512, 256);
    spmm_kernel<64><<<(NN + 1) / 2, 128>>>(tmp, cnt, bpack, b2, nullptr, act, 1, 1);

    // Layer 3: 256 -> 128
    gemm_mma_kernel<<<dim3(2, 391), 256, SMEM>>>(act, bthi + 393216, btlo + 393216, tmp, NN, 256, 128);
    spmm_kernel<32><<<(NN + 3) / 4, 128>>>(tmp, cnt, bpack, b3, nullptr, act, 1, 1);

    // Layer 4: 128 -> 64 (no ReLU, fp32 out)
    gemm_mma_kernel<<<dim3(1, 391), 256, SMEM>>>(act, bthi + 425984, btlo + 425984, tmp, NN, 128, 64);
    spmm_kernel<16><<<(NN + 7) / 8, 128>>>(tmp, cnt, bpack, b4, out, nullptr, 0, 0);

    (void)in_sizes; (void)n_in; (void)out_size;
}